// round 14
// baseline (speedup 1.0000x reference)
#include <cuda_runtime.h>
#include <cstddef>
#include <cstdint>

#define NN 100000
#define IN_DIM 256
#define H_DIM 128
#define C_DIM 40

// Scratch (device globals — no allocation allowed)
__device__ float g_h2[(size_t)NN * C_DIM];   // (relu(X@W1))@W2
__device__ float g_z1[(size_t)NN * C_DIM];   // first propagation
__device__ int   g_rowptr[NN + 1];           // CSR offsets from sorted edge_dst
__device__ float g_w1p[IN_DIM * H_DIM];      // W1 tf32, fragment-major permuted

// ---------------------------------------------------------------------------
// helpers
// ---------------------------------------------------------------------------
__device__ __forceinline__ float tf32r(float x) {
    uint32_t u;
    asm("cvt.rna.tf32.f32 %0, %1;" : "=r"(u) : "f"(x));
    return __uint_as_float(u);
}

__device__ __forceinline__ uint32_t tf32u(float x) {
    uint32_t u;
    asm("cvt.rna.tf32.f32 %0, %1;" : "=r"(u) : "f"(x));
    return u;
}

__device__ __forceinline__ void mma_tf32(float* c, const uint32_t* a,
                                         uint32_t b0, uint32_t b1) {
    asm volatile(
        "mma.sync.aligned.m16n8k8.row.col.f32.tf32.tf32.f32 "
        "{%0,%1,%2,%3}, {%4,%5,%6,%7}, {%8,%9}, {%0,%1,%2,%3};\n"
        : "+f"(c[0]), "+f"(c[1]), "+f"(c[2]), "+f"(c[3])
        : "r"(a[0]), "r"(a[1]), "r"(a[2]), "r"(a[3]), "r"(b0), "r"(b1));
}

__device__ __forceinline__ uint32_t smem_to_u32(const void* smem_ptr) {
    uint32_t addr;
    asm("{ .reg .u64 tmp; cvta.to.shared.u64 tmp, %1; cvt.u32.u64 %0, tmp; }"
        : "=r"(addr) : "l"(smem_ptr));
    return addr;
}

__device__ __forceinline__ void cp_async16(uint32_t dst, const void* src,
                                           int srcsize) {
    asm volatile("cp.async.ca.shared.global [%0], [%1], 16, %2;"
                 :: "r"(dst), "l"(src), "r"(srcsize));
}

__device__ __forceinline__ void cp_commit() {
    asm volatile("cp.async.commit_group;" ::: "memory");
}

template <int N>
__device__ __forceinline__ void cp_wait() {
    asm volatile("cp.async.wait_group %0;" :: "n"(N) : "memory");
}

// ---------------------------------------------------------------------------
// W1 -> tf32 fragment-major permute (one-time pre-pass, 32K elements).
// g_w1p[(((kt*4+kb)*2+wn)*32+lane)*16 + q], q = w*4 + c:
//   value = tf32(W1[k][n]),  k = kt*32 + kb*8 + (c&1)*4 + (lane&3)
//                            n = wn*64 + (2*w + (c>>1))*8 + (lane>>2)
// so per (kb,wn,lane) the thread's 16 B-fragment scalars are contiguous,
// in the order {b0,b1} x ni used by the mainloop's 4x float4 reads.
// ---------------------------------------------------------------------------
__global__ void w1_perm_kernel(const float* __restrict__ W1) {
    const int gid = blockIdx.x * blockDim.x + threadIdx.x;
    if (gid >= IN_DIM * H_DIM) return;
    const int q    = gid & 15;
    const int lane = (gid >> 4) & 31;
    const int wn   = (gid >> 9) & 1;
    const int kb   = (gid >> 10) & 3;
    const int kt   = gid >> 12;
    const int w = q >> 2, c = q & 3;
    const int k = kt * 32 + kb * 8 + (c & 1) * 4 + (lane & 3);
    const int n = wn * 64 + (2 * w + (c >> 1)) * 8 + (lane >> 2);
    g_w1p[gid] = tf32r(W1[(size_t)k * H_DIM + n]);
}

// ---------------------------------------------------------------------------
// Fused MLP: g_h2 = relu(X[M,256] @ W1[256,128]) @ W2[128,40]
// cp.async double-buffered; BM=128, warp tile 32x64, BK=32.
// B staged from pre-permuted g_w1p -> mainloop B = 4x LDS.128 per kb
// (20-float lane padding: banks conflict-free).
//
// smem (floats, union):
//   stage1: As[2][128][36] @0 (9216) | Bsp[2][5120] @9216 (10240) = 19456 f
//   stage2: H[128][132] @0 (16896)   | Ws[128][44] @16896 (5632)  = 22528 f
// total 90112 B
// ---------------------------------------------------------------------------
#define AS_STRIDE 36
#define AS_TILE_F (128 * AS_STRIDE)     // 4608
#define BS_BASE_F (2 * AS_TILE_F)       // 9216
#define BS_TILE_F 5120                  // 4kb x 2wn x 32lane x 20
#define S2_H_STRIDE 132
#define S2_W_STRIDE 44
#define FUSED_SMEM_BYTES 90112

extern __shared__ float sm[];

__global__ __launch_bounds__(256, 2) void fused_mlp_kernel(
    const float* __restrict__ A, const float* __restrict__ W2, int M) {
    const int tid = threadIdx.x;
    const int lane = tid & 31;
    const int wid = tid >> 5;
    const int blockRow = blockIdx.x;
    const uint32_t smem_base = smem_to_u32(sm);

    const int warp_m = wid >> 1;
    const int warp_n = wid & 1;

    float acc[2][8][4];
    #pragma unroll
    for (int mi = 0; mi < 2; mi++)
        #pragma unroll
        for (int ni = 0; ni < 8; ni++)
            #pragma unroll
            for (int q = 0; q < 4; q++) acc[mi][ni][q] = 0.f;

    auto stage_tile = [&](int buf, int kt) {
        const int k0 = kt * 32;
        #pragma unroll
        for (int t = 0; t < 4; t++) {
            const int f4 = tid + t * 256;
            // A: 128 rows x 8 f4 per row
            const int row = f4 >> 3, kc4 = (f4 & 7) * 4;
            const int arow = blockRow * 128 + row;
            const int ok = (arow < M) ? 16 : 0;
            const float* srcA =
                A + (size_t)(ok ? arow : 0) * IN_DIM + k0 + kc4;
            cp_async16(smem_base +
                           (uint32_t)(buf * AS_TILE_F + row * AS_STRIDE + kc4) * 4,
                       srcA, ok);
            // B: 1024 chunks of 16B from permuted g_w1p (dense, coalesced)
            const int qg  = f4 & 3;
            const int ln  = (f4 >> 2) & 31;
            const int wnb = (f4 >> 7) & 1;
            const int kbb = f4 >> 8;
            const float* srcB = g_w1p + (size_t)kt * 4096 + f4 * 4;
            cp_async16(smem_base +
                           (uint32_t)(BS_BASE_F + buf * BS_TILE_F +
                                      ((kbb * 2 + wnb) * 32 + ln) * 20 + qg * 4) * 4,
                       srcB, 16);
        }
        cp_commit();
    };

    stage_tile(0, 0);

    int cur = 0;
    constexpr int NKT = IN_DIM / 32;  // 8
    for (int kt = 0; kt < NKT; kt++) {
        if (kt < NKT - 1) {
            stage_tile(1 - cur, kt + 1);
            cp_wait<1>();
        } else {
            cp_wait<0>();
        }
        __syncthreads();

        const float* Ac = sm + cur * AS_TILE_F;
        const float* Bc = sm + BS_BASE_F + cur * BS_TILE_F;
        #pragma unroll
        for (int kb = 0; kb < 4; kb++) {
            const int kk = kb * 8;
            uint32_t af[2][4];
            #pragma unroll
            for (int mi = 0; mi < 2; mi++) {
                const int rb = warp_m * 32 + mi * 16 + (lane >> 2);
                const int kc = kk + (lane & 3);
                af[mi][0] = tf32u(Ac[rb * AS_STRIDE + kc]);
                af[mi][1] = tf32u(Ac[(rb + 8) * AS_STRIDE + kc]);
                af[mi][2] = tf32u(Ac[rb * AS_STRIDE + kc + 4]);
                af[mi][3] = tf32u(Ac[(rb + 8) * AS_STRIDE + kc + 4]);
            }
            const float* Bb = Bc + ((kb * 2 + warp_n) * 32 + lane) * 20;
            const float4 bv0 = *reinterpret_cast<const float4*>(Bb);
            const float4 bv1 = *reinterpret_cast<const float4*>(Bb + 4);
            const float4 bv2 = *reinterpret_cast<const float4*>(Bb + 8);
            const float4 bv3 = *reinterpret_cast<const float4*>(Bb + 12);
            #pragma unroll
            for (int mi = 0; mi < 2; mi++) {
                mma_tf32(acc[mi][0], af[mi], __float_as_uint(bv0.x), __float_as_uint(bv0.y));
                mma_tf32(acc[mi][1], af[mi], __float_as_uint(bv0.z), __float_as_uint(bv0.w));
                mma_tf32(acc[mi][2], af[mi], __float_as_uint(bv1.x), __float_as_uint(bv1.y));
                mma_tf32(acc[mi][3], af[mi], __float_as_uint(bv1.z), __float_as_uint(bv1.w));
                mma_tf32(acc[mi][4], af[mi], __float_as_uint(bv2.x), __float_as_uint(bv2.y));
                mma_tf32(acc[mi][5], af[mi], __float_as_uint(bv2.z), __float_as_uint(bv2.w));
                mma_tf32(acc[mi][6], af[mi], __float_as_uint(bv3.x), __float_as_uint(bv3.y));
                mma_tf32(acc[mi][7], af[mi], __float_as_uint(bv3.z), __float_as_uint(bv3.w));
            }
        }
        __syncthreads();
        cur = 1 - cur;
    }

    // ---- stage 1 -> stage 2 transition (smem overlay) ----
    float* H  = sm;                      // [128][132]
    float* Ws = sm + 128 * S2_H_STRIDE;  // [128][44]

    #pragma unroll
    for (int mi = 0; mi < 2; mi++) {
        const int r0 = warp_m * 32 + mi * 16 + (lane >> 2);
        #pragma unroll
        for (int ni = 0; ni < 8; ni++) {
            const int c0 = warp_n * 64 + ni * 8 + 2 * (lane & 3);
            H[r0 * S2_H_STRIDE + c0]           = tf32r(fmaxf(acc[mi][ni][0], 0.f));
            H[r0 * S2_H_STRIDE + c0 + 1]       = tf32r(fmaxf(acc[mi][ni][1], 0.f));
            H[(r0 + 8) * S2_H_STRIDE + c0]     = tf32r(fmaxf(acc[mi][ni][2], 0.f));
            H[(r0 + 8) * S2_H_STRIDE + c0 + 1] = tf32r(fmaxf(acc[mi][ni][3], 0.f));
        }
    }
    for (int i = tid; i < H_DIM * C_DIM; i += 256)
        Ws[(i / C_DIM) * S2_W_STRIDE + (i % C_DIM)] = tf32r(W2[i]);
    __syncthreads();

    // ---- stage 2: h2 = H @ W2, each of 8 warps does 16 rows, K=128 ----
    const int rb2 = wid * 16;
    float acc2[5][4];
    #pragma unroll
    for (int ni = 0; ni < 5; ni++)
        #pragma unroll
        for (int q = 0; q < 4; q++) acc2[ni][q] = 0.f;

    #pragma unroll
    for (int k8 = 0; k8 < 16; k8++) {
        const int kk = k8 * 8;
        uint32_t af[4];
        const int rr = rb2 + (lane >> 2);
        const int kc = kk + (lane & 3);
        af[0] = __float_as_uint(H[rr * S2_H_STRIDE + kc]);
        af[1] = __float_as_uint(H[(rr + 8) * S2_H_STRIDE + kc]);
        af[2] = __float_as_uint(H[rr * S2_H_STRIDE + kc + 4]);
        af[3] = __float_as_uint(H[(rr + 8) * S2_H_STRIDE + kc + 4]);
        #pragma unroll
        for (int ni = 0; ni < 5; ni++) {
            const int nb = ni * 8 + (lane >> 2);
            const uint32_t b0 =
                __float_as_uint(Ws[(kk + (lane & 3)) * S2_W_STRIDE + nb]);
            const uint32_t b1 =
                __float_as_uint(Ws[(kk + 4 + (lane & 3)) * S2_W_STRIDE + nb]);
            mma_tf32(acc2[ni], af, b0, b1);
        }
    }

    const int row0 = blockRow * 128 + rb2 + (lane >> 2);
    #pragma unroll
    for (int ni = 0; ni < 5; ni++) {
        const int c0 = ni * 8 + 2 * (lane & 3);
        if (row0 < M) {
            float2 v = make_float2(acc2[ni][0], acc2[ni][1]);
            *reinterpret_cast<float2*>(g_h2 + (size_t)row0 * C_DIM + c0) = v;
        }
        if (row0 + 8 < M) {
            float2 v = make_float2(acc2[ni][2], acc2[ni][3]);
            *reinterpret_cast<float2*>(g_h2 + (size_t)(row0 + 8) * C_DIM + c0) = v;
        }
    }
}

// ---------------------------------------------------------------------------
// Row-pointer build: edge_dst is SORTED. rowptr[v] = lower_bound(dst, v).
// ---------------------------------------------------------------------------
__global__ void rowptr_kernel(const int* __restrict__ dst, int N, int E) {
    const int v = blockIdx.x * blockDim.x + threadIdx.x;
    if (v > N) return;
    int lo = 0, hi = E;
    while (lo < hi) {
        const int mid = (lo + hi) >> 1;
        if (__ldg(dst + mid) < v) lo = mid + 1; else hi = mid;
    }
    g_rowptr[v] = lo;
}

// ---------------------------------------------------------------------------
// CSR SPMM (exact R11 config — best measured 36.6 us):
// 320 threads = 32 groups x 10 lanes; group owns one node; lane owns float4.
// 2-edge unroll. No atomics, no output zeroing.
// ---------------------------------------------------------------------------
__global__ __launch_bounds__(320) void spmm_csr_kernel(
    const int* __restrict__ src, const float* __restrict__ val,
    const float* __restrict__ x, float* __restrict__ out, int N) {
    const int tid = threadIdx.x;
    const int node = blockIdx.x * 32 + tid / 10;
    const int lane = tid % 10;
    if (node >= N) return;

    const int start = __ldg(g_rowptr + node);
    const int end   = __ldg(g_rowptr + node + 1);

    float4 a0 = make_float4(0.f, 0.f, 0.f, 0.f);
    float4 a1 = make_float4(0.f, 0.f, 0.f, 0.f);

    int i = start;
    for (; i + 2 <= end; i += 2) {
        const int   s0 = __ldg(src + i);
        const int   s1 = __ldg(src + i + 1);
        const float v0 = __ldg(val + i);
        const float v1 = __ldg(val + i + 1);
        const float4 x0 = *reinterpret_cast<const float4*>(
            x + (size_t)s0 * C_DIM + lane * 4);
        const float4 x1 = *reinterpret_cast<const float4*>(
            x + (size_t)s1 * C_DIM + lane * 4);
        a0.x = fmaf(v0, x0.x, a0.x); a0.y = fmaf(v0, x0.y, a0.y);
        a0.z = fmaf(v0, x0.z, a0.z); a0.w = fmaf(v0, x0.w, a0.w);
        a1.x = fmaf(v1, x1.x, a1.x); a1.y = fmaf(v1, x1.y, a1.y);
        a1.z = fmaf(v1, x1.z, a1.z); a1.w = fmaf(v1, x1.w, a1.w);
    }
    if (i < end) {
        const int   s0 = __ldg(src + i);
        const float v0 = __ldg(val + i);
        const float4 x0 = *reinterpret_cast<const float4*>(
            x + (size_t)s0 * C_DIM + lane * 4);
        a0.x = fmaf(v0, x0.x, a0.x); a0.y = fmaf(v0, x0.y, a0.y);
        a0.z = fmaf(v0, x0.z, a0.z); a0.w = fmaf(v0, x0.w, a0.w);
    }

    float4 r;
    r.x = a0.x + a1.x; r.y = a0.y + a1.y;
    r.z = a0.z + a1.z; r.w = a0.w + a1.w;
    *reinterpret_cast<float4*>(out + (size_t)node * C_DIM + lane * 4) = r;
}

extern "C" void kernel_launch(void* const* d_in, const int* in_sizes, int n_in,
                              void* d_out, int out_size) {
    const float* features = (const float*)d_in[0];
    const float* W1       = (const float*)d_in[1];
    const float* W2       = (const float*)d_in[2];
    const int*   edge_src = (const int*)d_in[3];
    const int*   edge_dst = (const int*)d_in[4];
    const float* edge_val = (const float*)d_in[5];
    float* out = (float*)d_out;

    const int M = in_sizes[0] / IN_DIM;   // 100000
    const int E = in_sizes[3];            // 1600000

    float *p_h2, *p_z1;
    cudaGetSymbolAddress((void**)&p_h2, g_h2);
    cudaGetSymbolAddress((void**)&p_z1, g_z1);

    static bool attr_set = false;
    if (!attr_set) {
        cudaFuncSetAttribute(fused_mlp_kernel,
                             cudaFuncAttributeMaxDynamicSharedMemorySize,
                             FUSED_SMEM_BYTES);
        attr_set = true;
    }

    // 0) W1 -> tf32 fragment-major permute
    w1_perm_kernel<<<(IN_DIM * H_DIM + 255) / 256, 256>>>(W1);

    // 1) h2 = relu(X @ W1) @ W2  (single fused kernel)
    fused_mlp_kernel<<<(M + 127) / 128, 256, FUSED_SMEM_BYTES>>>(
        features, W2, M);

    // 2) CSR row pointers from sorted edge_dst (shared by both propagations)
    rowptr_kernel<<<(M + 257) / 256, 256>>>(edge_dst, M, E);

    // 3) z1 = A @ h2 ; out = A @ z1   (no zeroing, no atomics)
    spmm_csr_kernel<<<(M + 31) / 32, 320>>>(edge_src, edge_val, p_h2, p_z1, M);
    spmm_csr_kernel<<<(M + 31) / 32, 320>>>(edge_src, edge_val, p_z1, out, M);
}

// round 15
// speedup vs baseline: 1.0559x; 1.0559x over previous
#include <cuda_runtime.h>
#include <cstddef>
#include <cstdint>

#define NN 100000
#define IN_DIM 256
#define H_DIM 128
#define C_DIM 40

// Scratch (device globals — no allocation allowed)
__device__ float g_h2[(size_t)NN * C_DIM];   // (relu(X@W1))@W2
__device__ float g_z1[(size_t)NN * C_DIM];   // first propagation
__device__ int   g_rowptr[NN + 1];           // CSR offsets from sorted edge_dst
__device__ float g_w1[IN_DIM * H_DIM];       // W1 pre-rounded to tf32

// ---------------------------------------------------------------------------
// helpers
// ---------------------------------------------------------------------------
__device__ __forceinline__ float tf32r(float x) {
    uint32_t u;
    asm("cvt.rna.tf32.f32 %0, %1;" : "=r"(u) : "f"(x));
    return __uint_as_float(u);
}

__device__ __forceinline__ uint32_t tf32u(float x) {
    uint32_t u;
    asm("cvt.rna.tf32.f32 %0, %1;" : "=r"(u) : "f"(x));
    return u;
}

__device__ __forceinline__ void mma_tf32(float* c, const uint32_t* a,
                                         uint32_t b0, uint32_t b1) {
    asm volatile(
        "mma.sync.aligned.m16n8k8.row.col.f32.tf32.tf32.f32 "
        "{%0,%1,%2,%3}, {%4,%5,%6,%7}, {%8,%9}, {%0,%1,%2,%3};\n"
        : "+f"(c[0]), "+f"(c[1]), "+f"(c[2]), "+f"(c[3])
        : "r"(a[0]), "r"(a[1]), "r"(a[2]), "r"(a[3]), "r"(b0), "r"(b1));
}

__device__ __forceinline__ uint32_t smem_to_u32(const void* smem_ptr) {
    uint32_t addr;
    asm("{ .reg .u64 tmp; cvta.to.shared.u64 tmp, %1; cvt.u32.u64 %0, tmp; }"
        : "=r"(addr) : "l"(smem_ptr));
    return addr;
}

__device__ __forceinline__ void cp_async16(uint32_t dst, const void* src,
                                           int srcsize) {
    asm volatile("cp.async.ca.shared.global [%0], [%1], 16, %2;"
                 :: "r"(dst), "l"(src), "r"(srcsize));
}

__device__ __forceinline__ void cp_commit() {
    asm volatile("cp.async.commit_group;" ::: "memory");
}

template <int N>
__device__ __forceinline__ void cp_wait() {
    asm volatile("cp.async.wait_group %0;" :: "n"(N) : "memory");
}

// ---------------------------------------------------------------------------
// W1 -> tf32 pre-pass (32K elements)
// ---------------------------------------------------------------------------
__global__ void w1_conv_kernel(const float* __restrict__ W1) {
    const int i = (blockIdx.x * blockDim.x + threadIdx.x) * 4;
    if (i < IN_DIM * H_DIM) {
        float4 v = *reinterpret_cast<const float4*>(W1 + i);
        float4 c;
        c.x = tf32r(v.x); c.y = tf32r(v.y);
        c.z = tf32r(v.z); c.w = tf32r(v.w);
        *reinterpret_cast<float4*>(g_w1 + i) = c;
    }
}

// ---------------------------------------------------------------------------
// Fused MLP (exact R13): cp.async double-buffered, BM=128, warp tile 32x64.
// ---------------------------------------------------------------------------
#define AS_STRIDE 36
#define BS_STRIDE 136
#define AS_TILE_F (128 * AS_STRIDE)     // 4608
#define BS_BASE_F (2 * AS_TILE_F)       // 9216
#define BS_TILE_F (32 * BS_STRIDE)      // 4352
#define S2_H_STRIDE 132
#define S2_W_STRIDE 44
#define FUSED_SMEM_BYTES 90112

extern __shared__ float sm[];

__global__ __launch_bounds__(256, 2) void fused_mlp_kernel(
    const float* __restrict__ A, const float* __restrict__ W2, int M) {
    const int tid = threadIdx.x;
    const int lane = tid & 31;
    const int wid = tid >> 5;
    const int blockRow = blockIdx.x;
    const uint32_t smem_base = smem_to_u32(sm);

    const int warp_m = wid >> 1;
    const int warp_n = wid & 1;

    float acc[2][8][4];
    #pragma unroll
    for (int mi = 0; mi < 2; mi++)
        #pragma unroll
        for (int ni = 0; ni < 8; ni++)
            #pragma unroll
            for (int q = 0; q < 4; q++) acc[mi][ni][q] = 0.f;

    auto stage_tile = [&](int buf, int k0) {
        #pragma unroll
        for (int t = 0; t < 4; t++) {
            const int f4 = tid + t * 256;
            const int row = f4 >> 3, kc4 = (f4 & 7) * 4;
            const int arow = blockRow * 128 + row;
            const int ok = (arow < M) ? 16 : 0;
            const float* srcA =
                A + (size_t)(ok ? arow : 0) * IN_DIM + k0 + kc4;
            cp_async16(smem_base +
                           (uint32_t)(buf * AS_TILE_F + row * AS_STRIDE + kc4) * 4,
                       srcA, ok);
            const int bk = f4 >> 5, nc = (f4 & 31) * 4;
            const float* srcB = g_w1 + (size_t)(k0 + bk) * H_DIM + nc;
            cp_async16(smem_base +
                           (uint32_t)(BS_BASE_F + buf * BS_TILE_F +
                                      bk * BS_STRIDE + nc) * 4,
                       srcB, 16);
        }
        cp_commit();
    };

    stage_tile(0, 0);

    int cur = 0;
    constexpr int NKT = IN_DIM / 32;  // 8
    for (int kt = 0; kt < NKT; kt++) {
        if (kt < NKT - 1) {
            stage_tile(1 - cur, (kt + 1) * 32);
            cp_wait<1>();
        } else {
            cp_wait<0>();
        }
        __syncthreads();

        const float* Ac = sm + cur * AS_TILE_F;
        const float* Bc = sm + BS_BASE_F + cur * BS_TILE_F;
        #pragma unroll
        for (int kb = 0; kb < 4; kb++) {
            const int kk = kb * 8;
            uint32_t af[2][4];
            #pragma unroll
            for (int mi = 0; mi < 2; mi++) {
                const int rb = warp_m * 32 + mi * 16 + (lane >> 2);
                const int kc = kk + (lane & 3);
                af[mi][0] = tf32u(Ac[rb * AS_STRIDE + kc]);
                af[mi][1] = tf32u(Ac[(rb + 8) * AS_STRIDE + kc]);
                af[mi][2] = tf32u(Ac[rb * AS_STRIDE + kc + 4]);
                af[mi][3] = tf32u(Ac[(rb + 8) * AS_STRIDE + kc + 4]);
            }
            #pragma unroll
            for (int ni = 0; ni < 8; ni++) {
                const int nb = warp_n * 64 + ni * 8 + (lane >> 2);
                const uint32_t b0 =
                    __float_as_uint(Bc[(kk + (lane & 3)) * BS_STRIDE + nb]);
                const uint32_t b1 =
                    __float_as_uint(Bc[(kk + 4 + (lane & 3)) * BS_STRIDE + nb]);
                mma_tf32(acc[0][ni], af[0], b0, b1);
                mma_tf32(acc[1][ni], af[1], b0, b1);
            }
        }
        __syncthreads();
        cur = 1 - cur;
    }

    // ---- stage 1 -> stage 2 transition (smem overlay) ----
    float* H  = sm;                      // [128][132]
    float* Ws = sm + 128 * S2_H_STRIDE;  // [128][44]

    #pragma unroll
    for (int mi = 0; mi < 2; mi++) {
        const int r0 = warp_m * 32 + mi * 16 + (lane >> 2);
        #pragma unroll
        for (int ni = 0; ni < 8; ni++) {
            const int c0 = warp_n * 64 + ni * 8 + 2 * (lane & 3);
            H[r0 * S2_H_STRIDE + c0]           = tf32r(fmaxf(acc[mi][ni][0], 0.f));
            H[r0 * S2_H_STRIDE + c0 + 1]       = tf32r(fmaxf(acc[mi][ni][1], 0.f));
            H[(r0 + 8) * S2_H_STRIDE + c0]     = tf32r(fmaxf(acc[mi][ni][2], 0.f));
            H[(r0 + 8) * S2_H_STRIDE + c0 + 1] = tf32r(fmaxf(acc[mi][ni][3], 0.f));
        }
    }
    for (int i = tid; i < H_DIM * C_DIM; i += 256)
        Ws[(i / C_DIM) * S2_W_STRIDE + (i % C_DIM)] = tf32r(W2[i]);
    __syncthreads();

    const int rb2 = wid * 16;
    float acc2[5][4];
    #pragma unroll
    for (int ni = 0; ni < 5; ni++)
        #pragma unroll
        for (int q = 0; q < 4; q++) acc2[ni][q] = 0.f;

    #pragma unroll
    for (int k8 = 0; k8 < 16; k8++) {
        const int kk = k8 * 8;
        uint32_t af[4];
        const int rr = rb2 + (lane >> 2);
        const int kc = kk + (lane & 3);
        af[0] = __float_as_uint(H[rr * S2_H_STRIDE + kc]);
        af[1] = __float_as_uint(H[(rr + 8) * S2_H_STRIDE + kc]);
        af[2] = __float_as_uint(H[rr * S2_H_STRIDE + kc + 4]);
        af[3] = __float_as_uint(H[(rr + 8) * S2_H_STRIDE + kc + 4]);
        #pragma unroll
        for (int ni = 0; ni < 5; ni++) {
            const int nb = ni * 8 + (lane >> 2);
            const uint32_t b0 =
                __float_as_uint(Ws[(kk + (lane & 3)) * S2_W_STRIDE + nb]);
            const uint32_t b1 =
                __float_as_uint(Ws[(kk + 4 + (lane & 3)) * S2_W_STRIDE + nb]);
            mma_tf32(acc2[ni], af, b0, b1);
        }
    }

    const int row0 = blockRow * 128 + rb2 + (lane >> 2);
    #pragma unroll
    for (int ni = 0; ni < 5; ni++) {
        const int c0 = ni * 8 + 2 * (lane & 3);
        if (row0 < M) {
            float2 v = make_float2(acc2[ni][0], acc2[ni][1]);
            *reinterpret_cast<float2*>(g_h2 + (size_t)row0 * C_DIM + c0) = v;
        }
        if (row0 + 8 < M) {
            float2 v = make_float2(acc2[ni][2], acc2[ni][3]);
            *reinterpret_cast<float2*>(g_h2 + (size_t)(row0 + 8) * C_DIM + c0) = v;
        }
    }
}

// ---------------------------------------------------------------------------
// Row-pointer build: edge_dst is SORTED. rowptr[v] = lower_bound(dst, v).
// ---------------------------------------------------------------------------
__global__ void rowptr_kernel(const int* __restrict__ dst, int N, int E) {
    const int v = blockIdx.x * blockDim.x + threadIdx.x;
    if (v > N) return;
    int lo = 0, hi = E;
    while (lo < hi) {
        const int mid = (lo + hi) >> 1;
        if (__ldg(dst + mid) < v) lo = mid + 1; else hi = mid;
    }
    g_rowptr[v] = lo;
}

// ---------------------------------------------------------------------------
// CSR SPMM with metadata software-pipelining:
// 320 threads = 32 groups x 10 lanes; group owns one node; lane owns float4.
// Next edge-pair's src/val loaded BETWEEN issuing gathers and consuming them,
// so metadata latency hides under the gather stall.
// No atomics, no output zeroing.
// ---------------------------------------------------------------------------
__global__ __launch_bounds__(320) void spmm_csr_kernel(
    const int* __restrict__ src, const float* __restrict__ val,
    const float* __restrict__ x, float* __restrict__ out, int N) {
    const int tid = threadIdx.x;
    const int node = blockIdx.x * 32 + tid / 10;
    const int lane = tid % 10;
    if (node >= N) return;

    const int start = __ldg(g_rowptr + node);
    const int end   = __ldg(g_rowptr + node + 1);

    float4 a0 = make_float4(0.f, 0.f, 0.f, 0.f);
    float4 a1 = make_float4(0.f, 0.f, 0.f, 0.f);

    int i = start;
    int s0 = 0, s1 = 0;
    float v0 = 0.f, v1 = 0.f;
    if (i + 2 <= end) {
        s0 = __ldg(src + i);     s1 = __ldg(src + i + 1);
        v0 = __ldg(val + i);     v1 = __ldg(val + i + 1);
    }
    while (i + 2 <= end) {
        // issue gathers for the current pair
        const float4 x0 = *reinterpret_cast<const float4*>(
            x + (size_t)s0 * C_DIM + lane * 4);
        const float4 x1 = *reinterpret_cast<const float4*>(
            x + (size_t)s1 * C_DIM + lane * 4);
        // prefetch next pair's metadata while gathers are in flight
        int ns0 = s0, ns1 = s1;
        float nv0 = v0, nv1 = v1;
        if (i + 4 <= end) {
            ns0 = __ldg(src + i + 2);  ns1 = __ldg(src + i + 3);
            nv0 = __ldg(val + i + 2);  nv1 = __ldg(val + i + 3);
        }
        // consume gathers
        a0.x = fmaf(v0, x0.x, a0.x); a0.y = fmaf(v0, x0.y, a0.y);
        a0.z = fmaf(v0, x0.z, a0.z); a0.w = fmaf(v0, x0.w, a0.w);
        a1.x = fmaf(v1, x1.x, a1.x); a1.y = fmaf(v1, x1.y, a1.y);
        a1.z = fmaf(v1, x1.z, a1.z); a1.w = fmaf(v1, x1.w, a1.w);
        s0 = ns0; s1 = ns1; v0 = nv0; v1 = nv1;
        i += 2;
    }
    if (i < end) {
        const int   ts = __ldg(src + i);
        const float tv = __ldg(val + i);
        const float4 x0 = *reinterpret_cast<const float4*>(
            x + (size_t)ts * C_DIM + lane * 4);
        a0.x = fmaf(tv, x0.x, a0.x); a0.y = fmaf(tv, x0.y, a0.y);
        a0.z = fmaf(tv, x0.z, a0.z); a0.w = fmaf(tv, x0.w, a0.w);
    }

    float4 r;
    r.x = a0.x + a1.x; r.y = a0.y + a1.y;
    r.z = a0.z + a1.z; r.w = a0.w + a1.w;
    *reinterpret_cast<float4*>(out + (size_t)node * C_DIM + lane * 4) = r;
}

extern "C" void kernel_launch(void* const* d_in, const int* in_sizes, int n_in,
                              void* d_out, int out_size) {
    const float* features = (const float*)d_in[0];
    const float* W1       = (const float*)d_in[1];
    const float* W2       = (const float*)d_in[2];
    const int*   edge_src = (const int*)d_in[3];
    const int*   edge_dst = (const int*)d_in[4];
    const float* edge_val = (const float*)d_in[5];
    float* out = (float*)d_out;

    const int M = in_sizes[0] / IN_DIM;   // 100000
    const int E = in_sizes[3];            // 1600000

    float *p_h2, *p_z1;
    cudaGetSymbolAddress((void**)&p_h2, g_h2);
    cudaGetSymbolAddress((void**)&p_z1, g_z1);

    static bool attr_set = false;
    if (!attr_set) {
        cudaFuncSetAttribute(fused_mlp_kernel,
                             cudaFuncAttributeMaxDynamicSharedMemorySize,
                             FUSED_SMEM_BYTES);
        attr_set = true;
    }

    // 0) W1 -> tf32 pre-pass
    w1_conv_kernel<<<(IN_DIM * H_DIM / 4 + 255) / 256, 256>>>(W1);

    // 1) h2 = relu(X @ W1) @ W2  (single fused kernel)
    fused_mlp_kernel<<<(M + 127) / 128, 256, FUSED_SMEM_BYTES>>>(
        features, W2, M);

    // 2) CSR row pointers from sorted edge_dst (shared by both propagations)
    rowptr_kernel<<<(M + 257) / 256, 256>>>(edge_dst, M, E);

    // 3) z1 = A @ h2 ; out = A @ z1   (no zeroing, no atomics)
    spmm_csr_kernel<<<(M + 31) / 32, 320>>>(edge_src, edge_val, p_h2, p_z1, M);
    spmm_csr_kernel<<<(M + 31) / 32, 320>>>(edge_src, edge_val, p_z1, out, M);
}